// round 14
// baseline (speedup 1.0000x reference)
#include <cuda_runtime.h>
#include <cuda_fp16.h>
#include <cstdint>

#define NN 100000
#define NE 600000
#define DD 128
#define NREL 1000
#define NLAYER 3
#define SCAN_B 1024
#define SCAN_NB ((NN + SCAN_B - 1) / SCAN_B)

// ---------------- scratch (static device globals; no allocs) ----------------
__device__ float g_Q[NN * DD];
__device__ float g_KV[NN * 256];  // per node: K row [0..127] then V row [128..255]
__device__ float g_S[NN * DD];
__device__ __half g_Erelh[NLAYER * NREL * DD];  // fp16 E tables, all layers
__device__ float g_gsum[DD];
__device__ int g_cnt[NN];
__device__ int g_incl[NN];
__device__ int g_part[SCAN_NB];
__device__ int g_rowptr[NN + 1];
__device__ int g_cursor[NN + 1];
__device__ int2 g_edge2[NE];  // dst-sorted (src, etype)
// pre-swizzled fp16 W images: 12 (3 layers x {Q,K,V,S})
__device__ __align__(16) unsigned char g_WimgH[12 * 32768];

__device__ __forceinline__ uint32_t smem_u32(const void* p) {
    uint32_t a;
    asm("{ .reg .u64 t; cvta.to.shared.u64 t, %1; cvt.u32.u64 %0, t; }" : "=r"(a) : "l"(p));
    return a;
}
__device__ __forceinline__ int swz(int row, int g16) {
    return row * 256 + ((g16 ^ (row & 7)) << 4);
}
__device__ __forceinline__ void ldm_x4(uint32_t& r0, uint32_t& r1, uint32_t& r2, uint32_t& r3,
                                       uint32_t addr) {
    asm volatile("ldmatrix.sync.aligned.m8n8.x4.shared.b16 {%0,%1,%2,%3}, [%4];"
                 : "=r"(r0), "=r"(r1), "=r"(r2), "=r"(r3)
                 : "r"(addr));
}
__device__ __forceinline__ void ldm_x4t(uint32_t& r0, uint32_t& r1, uint32_t& r2, uint32_t& r3,
                                        uint32_t addr) {
    asm volatile("ldmatrix.sync.aligned.m8n8.x4.trans.shared.b16 {%0,%1,%2,%3}, [%4];"
                 : "=r"(r0), "=r"(r1), "=r"(r2), "=r"(r3)
                 : "r"(addr));
}
__device__ __forceinline__ void mma_f16(float* c, const uint32_t* a, uint32_t b0, uint32_t b1) {
    asm volatile(
        "mma.sync.aligned.m16n8k16.row.col.f32.f16.f16.f32 "
        "{%0,%1,%2,%3}, {%4,%5,%6,%7}, {%8,%9}, {%0,%1,%2,%3};"
        : "+f"(c[0]), "+f"(c[1]), "+f"(c[2]), "+f"(c[3])
        : "r"(a[0]), "r"(a[1]), "r"(a[2]), "r"(a[3]), "r"(b0), "r"(b1));
}
__device__ __forceinline__ void cpa16(uint32_t dst, const void* src) {
    asm volatile("cp.async.cg.shared.global [%0], [%1], 16;" ::"r"(dst), "l"(src));
}
__device__ __forceinline__ void cpa_commit() {
    asm volatile("cp.async.commit_group;" ::: "memory");
}
template <int N>
__device__ __forceinline__ void cpa_wait() {
    asm volatile("cp.async.wait_group %0;" ::"n"(N) : "memory");
}
__device__ __forceinline__ float4 h4_to_f4(uint2 r) {
    float2 fa = __half22float2(*(__half2*)&r.x);
    float2 fb = __half22float2(*(__half2*)&r.y);
    return make_float4(fa.x, fa.y, fb.x, fb.y);
}

// ---------------- init: x = ent_emb[node_ids]; fused cnt/gsum zero ----------------
__global__ void k_gather(const int* __restrict__ ids, const float* __restrict__ emb,
                         float* __restrict__ x) {
    int i = blockIdx.x * blockDim.x + threadIdx.x;
    if (i < NN) g_cnt[i] = 0;
    if (i < DD) g_gsum[i] = 0.f;
    if (i >= NN * 32) return;
    int n = i >> 5, l = i & 31;
    ((float4*)x)[n * 32 + l] = ((const float4*)emb)[(long long)ids[n] * 32 + l];
}

// ---------------- CSR build (dst-sorted) ----------------
__global__ void k_count(const int* __restrict__ dst) {
    int e = blockIdx.x * blockDim.x + threadIdx.x;
    if (e < NE) atomicAdd(&g_cnt[dst[e]], 1);
}

__global__ void k_scan1() {
    __shared__ int sh[SCAN_B];
    int i = blockIdx.x * SCAN_B + threadIdx.x;
    int v = (i < NN) ? g_cnt[i] : 0;
    sh[threadIdx.x] = v;
    __syncthreads();
    for (int off = 1; off < SCAN_B; off <<= 1) {
        int t = (threadIdx.x >= off) ? sh[threadIdx.x - off] : 0;
        __syncthreads();
        sh[threadIdx.x] += t;
        __syncthreads();
    }
    if (i < NN) g_incl[i] = sh[threadIdx.x];
    if (threadIdx.x == SCAN_B - 1) g_part[blockIdx.x] = sh[SCAN_B - 1];
}

// scan2 folded in: each block reduces the raw per-block sums before its own id.
__global__ void k_scan3() {
    __shared__ int spre;
    if (threadIdx.x == 0) spre = 0;
    __syncthreads();
    int pre = 0;
    for (int j = threadIdx.x; j < blockIdx.x; j += 128) pre += g_part[j];
    if (threadIdx.x < 128 && pre) atomicAdd(&spre, pre);
    __syncthreads();
    int base = spre;
    int i = blockIdx.x * SCAN_B + threadIdx.x;
    if (i < NN) {
        int v = g_incl[i] + base;
        g_rowptr[i + 1] = v;
        g_cursor[i + 1] = v;
        if (i == 0) { g_rowptr[0] = 0; g_cursor[0] = 0; }
    }
}

__global__ void k_scatter(const int* __restrict__ src, const int* __restrict__ dst,
                          const int* __restrict__ etype) {
    int e = blockIdx.x * blockDim.x + threadIdx.x;
    if (e < NE) {
        int p = atomicAdd(&g_cursor[dst[e]], 1);
        g_edge2[p] = make_int2(src[e], etype[e]);
    }
}

// ---------------- once: W -> pre-swizzled fp16 images ----------------
__global__ void k_wconv(const float* __restrict__ Wq, const float* __restrict__ Wk,
                        const float* __restrict__ Wv, const float* __restrict__ Ws) {
    int img = blockIdx.x;  // 0..11
    int l = img >> 2, m = img & 3;
    const float* W =
        ((m == 0) ? Wq : (m == 1) ? Wk : (m == 2) ? Wv : Ws) + (long long)l * DD * DD;
    unsigned char* hi = g_WimgH + img * 32768;
    for (int i = threadIdx.x; i < DD * DD; i += blockDim.x) {
        int k = i >> 7, n = i & 127;  // B(k,n) = W[k][n]
        float w = W[k * DD + n];
        int o = swz(k, n >> 3) + (n & 7) * 2;
        *(__half*)(hi + o) = __float2half(w);
    }
}

// ---------------- all layers: relation projection tables (3 x 1000 x 128) ----------
__global__ void k_erel3(const float* __restrict__ rel, const float* __restrict__ We,
                        const float* __restrict__ be) {
    __shared__ float sr[DD];
    int l = blockIdx.x / NREL, r = blockIdx.x % NREL, j = threadIdx.x;
    const float* W = We + (long long)l * DD * DD;
    sr[j] = rel[r * DD + j];
    __syncthreads();
    float acc = be[l * DD + j];
#pragma unroll 8
    for (int i = 0; i < DD; i++) acc = fmaf(sr[i], W[i * DD + j], acc);
    g_Erelh[(l * NREL + r) * DD + j] = __float2half(acc);
}

// ---------------- mma.sync fused Q/K/V/Skip GEMM (fp16 x fp16, fp32 accum) ------
// CTA = 128 rows x 128 cols (R12 shape); double-buffered B, 2 CTAs/SM.
#define SM_BIAS 0
#define SM_A 2048
#define SM_B0 (SM_A + 32768)
#define SM_B1 (SM_B0 + 32768)
#define SM_TOT (SM_B1 + 32768)

__device__ __forceinline__ void copyB_async(uint32_t sbdst, int img, int t) {
    const unsigned char* sh = g_WimgH + img * 32768;
#pragma unroll
    for (int i = 0; i < 8; i++) {
        int o = (t + i * 256) * 16;
        cpa16(sbdst + o, sh + o);
    }
}

__global__ void __launch_bounds__(256, 2)
k_qkvs_mma(const float* __restrict__ x, const float* __restrict__ bq,
           const float* __restrict__ bk, const float* __restrict__ bv,
           const float* __restrict__ bs, int layer) {
    extern __shared__ unsigned char smem[];
    uint32_t sb = smem_u32(smem);
    int t = threadIdx.x, w = t >> 5, lane = t & 31;
    int wr = w & 3, wc = w >> 2;  // 4 row-groups (32 rows) x 2 col-groups (64 cols)
    int rowBase = blockIdx.x * 128;

    copyB_async(sb + SM_B0, layer * 4 + 0, t);
    cpa_commit();  // G0

    if (t < 128) {
        float* bsm = (float*)(smem + SM_BIAS);
        bsm[t] = bq[t];
        bsm[128 + t] = bk[t];
        bsm[256 + t] = bv[t];
        bsm[384 + t] = bs[t];
    }

    // A tile: fp32 x -> fp16, swizzled smem
#pragma unroll
    for (int it = 0; it < 16; it++) {
        int f4 = t + it * 256;
        int r = f4 >> 5, c4 = (f4 & 31) << 2;
        float4 v = make_float4(0.f, 0.f, 0.f, 0.f);
        if (rowBase + r < NN) v = *(const float4*)&x[(long long)(rowBase + r) * 128 + c4];
        uint2 hp;
        __half2 h01 = __floats2half2_rn(v.x, v.y);
        __half2 h23 = __floats2half2_rn(v.z, v.w);
        hp.x = *(uint32_t*)&h01;
        hp.y = *(uint32_t*)&h23;
        int o = swz(r, c4 >> 3) + (c4 & 7) * 2;
        *(uint2*)(smem + SM_A + o) = hp;
    }

    copyB_async(sb + SM_B1, layer * 4 + 1, t);
    cpa_commit();  // G1

    for (int mi = 0; mi < 4; mi++) {
        if (mi < 3) cpa_wait<1>();  // B(mi) complete; B(mi+1) may be in flight
        else cpa_wait<0>();
        __syncthreads();
        uint32_t bcur = sb + ((mi & 1) ? SM_B1 : SM_B0);

        float acc[2][8][4];
#pragma unroll
        for (int a = 0; a < 2; a++)
#pragma unroll
            for (int i = 0; i < 8; i++)
#pragma unroll
                for (int j = 0; j < 4; j++) acc[a][i][j] = 0.f;

        int arow0 = wr * 32 + (lane & 15);
        int bmat = lane >> 3;
        int brow_in = ((bmat & 1) << 3) + (lane & 7);
        int bghalf = bmat >> 1;

#pragma unroll
        for (int ks = 0; ks < 8; ks++) {
            uint32_t ah[2][4];
            int ag = ks * 2 + (lane >> 4);
#pragma unroll
            for (int mt = 0; mt < 2; mt++) {
                uint32_t aaddr = sb + SM_A + swz(arow0 + mt * 16, ag);
                ldm_x4(ah[mt][0], ah[mt][1], ah[mt][2], ah[mt][3], aaddr);
            }
            int brow = ks * 16 + brow_in;
#pragma unroll
            for (int np = 0; np < 4; np++) {
                uint32_t bh0, bh1, bh2, bh3;
                uint32_t baddr = bcur + swz(brow, wc * 8 + np * 2 + bghalf);
                ldm_x4t(bh0, bh1, bh2, bh3, baddr);
#pragma unroll
                for (int mt = 0; mt < 2; mt++) {
                    mma_f16(acc[mt][np * 2], ah[mt], bh0, bh1);
                    mma_f16(acc[mt][np * 2 + 1], ah[mt], bh2, bh3);
                }
            }
        }

        __syncthreads();  // all warps done reading buf(mi&1)
        if (mi + 2 < 4) {
            copyB_async(sb + ((mi & 1) ? SM_B1 : SM_B0), layer * 4 + mi + 2, t);
            cpa_commit();
        }

        // epilogue; K/V interleave into g_KV (K at +0, V at +128; row stride 256)
        float* outp;
        int rstride;
        if (mi == 0) { outp = g_Q; rstride = 128; }
        else if (mi == 1) { outp = g_KV; rstride = 256; }
        else if (mi == 2) { outp = g_KV + 128; rstride = 256; }
        else { outp = g_S; rstride = 128; }
        const float* bsm = (const float*)(smem + SM_BIAS) + mi * 128;
        int cb = wc * 64 + (lane & 3) * 2;
#pragma unroll
        for (int mt = 0; mt < 2; mt++) {
            int r0 = rowBase + wr * 32 + mt * 16 + (lane >> 2);
#pragma unroll
            for (int nt = 0; nt < 8; nt++) {
                int col = cb + nt * 8;
                float2 b2 = make_float2(bsm[col], bsm[col + 1]);
                if (r0 < NN) {
                    float2 o0 = make_float2(acc[mt][nt][0] + b2.x, acc[mt][nt][1] + b2.y);
                    *(float2*)&outp[(long long)r0 * rstride + col] = o0;
                }
                if (r0 + 8 < NN) {
                    float2 o1 = make_float2(acc[mt][nt][2] + b2.x, acc[mt][nt][3] + b2.y);
                    *(float2*)&outp[(long long)(r0 + 8) * rstride + col] = o1;
                }
            }
        }
    }
}

// ---------------- fused attention / softmax / aggregate / LN / residual ----------------
// NN = 100000 = 12500 blocks * 8 warps exactly. 4-edge unrolled online softmax (R9 form).
__global__ void k_attn(float* __restrict__ x, const float* __restrict__ lng,
                       const float* __restrict__ lnb, int ebase, int last) {
    __shared__ float sums[DD];
    int n = blockIdx.x * (blockDim.x >> 5) + (threadIdx.x >> 5);
    int lane = threadIdx.x & 31;

    const float4* Q4 = (const float4*)g_Q;
    const float4* KV4 = (const float4*)g_KV;

    float4 q = Q4[n * 32 + lane];
    int beg = g_rowptr[n], end = g_rowptr[n + 1];

    float m = -3.4e38f, dsum = 0.f;
    float4 acc = make_float4(0.f, 0.f, 0.f, 0.f);

    int idx = beg;
#define EDGE_LOAD(i, e)                                                    \
    float4 kv##i = KV4[(e).x * 64 + lane];                                 \
    float4 vv##i = KV4[(e).x * 64 + 32 + lane];                            \
    uint2 er##i = *(const uint2*)&g_Erelh[ebase + (e).y * 128 + lane * 4]; \
    float4 ev##i = h4_to_f4(er##i);
#define EDGE_DOT(i)                                                      \
    float p##i = q.x * (kv##i.x + ev##i.x) + q.y * (kv##i.y + ev##i.y) + \
                 q.z * (kv##i.z + ev##i.z) + q.w * (kv##i.w + ev##i.w);  \
    p##i += __shfl_xor_sync(0xffffffffu, p##i, 1);                       \
    p##i += __shfl_xor_sync(0xffffffffu, p##i, 2);                       \
    float a##i = p##i * 0.25f;
#define EDGE_ACC(i)                      \
    acc.x += w##i * (vv##i.x + ev##i.x); \
    acc.y += w##i * (vv##i.y + ev##i.y); \
    acc.z += w##i * (vv##i.z + ev##i.z); \
    acc.w += w##i * (vv##i.w + ev##i.w);

    for (; idx + 3 < end; idx += 4) {
        int2 e0 = g_edge2[idx];
        int2 e1 = g_edge2[idx + 1];
        int2 e2 = g_edge2[idx + 2];
        int2 e3 = g_edge2[idx + 3];
        EDGE_LOAD(0, e0) EDGE_LOAD(1, e1) EDGE_LOAD(2, e2) EDGE_LOAD(3, e3)
        EDGE_DOT(0) EDGE_DOT(1) EDGE_DOT(2) EDGE_DOT(3)
        float mn = fmaxf(fmaxf(m, fmaxf(a0, a1)), fmaxf(a2, a3));
        float sc = __expf(m - mn);
        float w0 = __expf(a0 - mn), w1 = __expf(a1 - mn);
        float w2 = __expf(a2 - mn), w3 = __expf(a3 - mn);
        dsum = dsum * sc + w0 + w1 + w2 + w3;
        acc.x *= sc; acc.y *= sc; acc.z *= sc; acc.w *= sc;
        EDGE_ACC(0) EDGE_ACC(1) EDGE_ACC(2) EDGE_ACC(3)
        m = mn;
    }
    for (; idx < end; idx++) {
        int2 e0 = g_edge2[idx];
        EDGE_LOAD(0, e0)
        EDGE_DOT(0)
        float mn = fmaxf(m, a0);
        float sc = __expf(m - mn);
        float w0 = __expf(a0 - mn);
        dsum = dsum * sc + w0;
        acc.x *= sc; acc.y *= sc; acc.z *= sc; acc.w *= sc;
        EDGE_ACC(0)
        m = mn;
    }

    float inv = (dsum > 0.f) ? (1.f / dsum) : 0.f;
    float4 sk = ((const float4*)g_S)[n * 32 + lane];
    float4 o = make_float4(acc.x * inv + sk.x, acc.y * inv + sk.y, acc.z * inv + sk.z,
                           acc.w * inv + sk.w);

    float sum = o.x + o.y + o.z + o.w;
#pragma unroll
    for (int off = 16; off; off >>= 1) sum += __shfl_xor_sync(0xffffffffu, sum, off);
    float mean = sum * (1.f / 128.f);
    float4 c = make_float4(o.x - mean, o.y - mean, o.z - mean, o.w - mean);
    float ss = c.x * c.x + c.y * c.y + c.z * c.z + c.w * c.w;
#pragma unroll
    for (int off = 16; off; off >>= 1) ss += __shfl_xor_sync(0xffffffffu, ss, off);
    float var = ss * (1.f / 128.f);
    float rstd = rsqrtf(var + 1e-5f);

    float4 g = ((const float4*)lng)[lane];
    float4 b = ((const float4*)lnb)[lane];
    float4 y;
    y.x = fmaxf(c.x * rstd * g.x + b.x, 0.f);
    y.y = fmaxf(c.y * rstd * g.y + b.y, 0.f);
    y.z = fmaxf(c.z * rstd * g.z + b.z, 0.f);
    y.w = fmaxf(c.w * rstd * g.w + b.w, 0.f);

    float4 xo = ((float4*)x)[n * 32 + lane];
    xo.x += y.x;
    xo.y += y.y;
    xo.z += y.z;
    xo.w += y.w;
    ((float4*)x)[n * 32 + lane] = xo;

    if (last) {
        if (threadIdx.x < DD) sums[threadIdx.x] = 0.f;
        __syncthreads();
        atomicAdd(&sums[lane * 4 + 0], xo.x);
        atomicAdd(&sums[lane * 4 + 1], xo.y);
        atomicAdd(&sums[lane * 4 + 2], xo.z);
        atomicAdd(&sums[lane * 4 + 3], xo.w);
        __syncthreads();
        if (threadIdx.x < DD) atomicAdd(&g_gsum[threadIdx.x], sums[threadIdx.x]);
    }
}

__global__ void k_final(float* __restrict__ gout) {
    int c = threadIdx.x;
    if (c < DD) gout[c] = g_gsum[c] * (1.f / (float)NN);
}

// ---------------- launch ----------------
extern "C" void kernel_launch(void* const* d_in, const int* in_sizes, int n_in,
                              void* d_out, int out_size) {
    const int* node_ids = (const int*)d_in[0];
    const int* edge_index = (const int*)d_in[1];
    const int* edge_type = (const int*)d_in[2];
    const float* ent_emb = (const float*)d_in[3];
    const float* rel_emb = (const float*)d_in[4];
    const float* Wq = (const float*)d_in[5];
    const float* bq = (const float*)d_in[6];
    const float* Wk = (const float*)d_in[7];
    const float* bk = (const float*)d_in[8];
    const float* Wv = (const float*)d_in[9];
    const float* bv = (const float*)d_in[10];
    const float* We = (const float*)d_in[11];
    const float* be = (const float*)d_in[12];
    const float* Ws = (const float*)d_in[13];
    const float* bs = (const float*)d_in[14];
    const float* lng = (const float*)d_in[15];
    const float* lnb = (const float*)d_in[16];

    float* x = (float*)d_out;
    float* gout = (float*)d_out + (out_size - DD);

    const int* src = edge_index;
    const int* dst = edge_index + NE;

    cudaFuncSetAttribute(k_qkvs_mma, cudaFuncAttributeMaxDynamicSharedMemorySize, SM_TOT);

    // launches 1-4: keep layer-0 GEMM in the ncu capture slot (4th launch)
    k_gather<<<(NN * 32 + 255) / 256, 256>>>(node_ids, ent_emb, x);
    k_wconv<<<12, 256>>>(Wq, Wk, Wv, Ws);
    k_erel3<<<NLAYER * NREL, DD>>>(rel_emb, We, be);
    k_qkvs_mma<<<(NN + 127) / 128, 256, SM_TOT>>>(x, bq, bk, bv, bs, 0);

    // CSR build (needed before first k_attn)
    k_count<<<(NE + 255) / 256, 256>>>(dst);
    k_scan1<<<SCAN_NB, SCAN_B>>>();
    k_scan3<<<SCAN_NB, SCAN_B>>>();
    k_scatter<<<(NE + 255) / 256, 256>>>(src, dst, edge_type);

    k_attn<<<NN / 8, 256>>>(x, lng, lnb, 0, 0);

    for (int l = 1; l < NLAYER; l++) {
        int bo = l * DD;
        k_qkvs_mma<<<(NN + 127) / 128, 256, SM_TOT>>>(x, bq + bo, bk + bo, bv + bo, bs + bo, l);
        k_attn<<<NN / 8, 256>>>(x, lng + bo, lnb + bo, l * NREL * DD, l == NLAYER - 1);
    }

    k_final<<<1, DD>>>(gout);
}

// round 15
// speedup vs baseline: 1.0315x; 1.0315x over previous
#include <cuda_runtime.h>
#include <cuda_fp16.h>
#include <cstdint>

#define NN 100000
#define NE 600000
#define DD 128
#define NREL 1000
#define NLAYER 3
#define SCAN_B 1024
#define SCAN_NB ((NN + SCAN_B - 1) / SCAN_B)

// ---------------- scratch (static device globals; no allocs) ----------------
__device__ float g_Q[NN * DD];
__device__ float g_KV[NN * 256];  // per node: K row [0..127] then V row [128..255]
__device__ float g_S[NN * DD];
__device__ __half g_Erelh[NLAYER * NREL * DD];  // fp16 E tables, all layers
__device__ float g_gsum[DD];
__device__ int g_cnt[NN];
__device__ int g_incl[NN];
__device__ int g_part[SCAN_NB];
__device__ int g_rowptr[NN + 1];
__device__ int g_cursor[NN + 1];
__device__ int2 g_edge2[NE];  // dst-sorted (src, etype)
// pre-swizzled fp16 W images: 12 (3 layers x {Q,K,V,S})
__device__ __align__(16) unsigned char g_WimgH[12 * 32768];

__device__ __forceinline__ uint32_t smem_u32(const void* p) {
    uint32_t a;
    asm("{ .reg .u64 t; cvta.to.shared.u64 t, %1; cvt.u32.u64 %0, t; }" : "=r"(a) : "l"(p));
    return a;
}
__device__ __forceinline__ int swz(int row, int g16) {
    return row * 256 + ((g16 ^ (row & 7)) << 4);
}
__device__ __forceinline__ void ldm_x4(uint32_t& r0, uint32_t& r1, uint32_t& r2, uint32_t& r3,
                                       uint32_t addr) {
    asm volatile("ldmatrix.sync.aligned.m8n8.x4.shared.b16 {%0,%1,%2,%3}, [%4];"
                 : "=r"(r0), "=r"(r1), "=r"(r2), "=r"(r3)
                 : "r"(addr));
}
__device__ __forceinline__ void ldm_x4t(uint32_t& r0, uint32_t& r1, uint32_t& r2, uint32_t& r3,
                                        uint32_t addr) {
    asm volatile("ldmatrix.sync.aligned.m8n8.x4.trans.shared.b16 {%0,%1,%2,%3}, [%4];"
                 : "=r"(r0), "=r"(r1), "=r"(r2), "=r"(r3)
                 : "r"(addr));
}
__device__ __forceinline__ void mma_f16(float* c, const uint32_t* a, uint32_t b0, uint32_t b1) {
    asm volatile(
        "mma.sync.aligned.m16n8k16.row.col.f32.f16.f16.f32 "
        "{%0,%1,%2,%3}, {%4,%5,%6,%7}, {%8,%9}, {%0,%1,%2,%3};"
        : "+f"(c[0]), "+f"(c[1]), "+f"(c[2]), "+f"(c[3])
        : "r"(a[0]), "r"(a[1]), "r"(a[2]), "r"(a[3]), "r"(b0), "r"(b1));
}
__device__ __forceinline__ void cpa16(uint32_t dst, const void* src) {
    asm volatile("cp.async.cg.shared.global [%0], [%1], 16;" ::"r"(dst), "l"(src));
}
__device__ __forceinline__ void cpa_commit() {
    asm volatile("cp.async.commit_group;" ::: "memory");
}
template <int N>
__device__ __forceinline__ void cpa_wait() {
    asm volatile("cp.async.wait_group %0;" ::"n"(N) : "memory");
}
__device__ __forceinline__ float4 h4_to_f4(uint2 r) {
    float2 fa = __half22float2(*(__half2*)&r.x);
    float2 fb = __half22float2(*(__half2*)&r.y);
    return make_float4(fa.x, fa.y, fb.x, fb.y);
}

// ---------------- init: x = ent_emb[node_ids]; fused cnt/gsum zero ----------------
__global__ void k_gather(const int* __restrict__ ids, const float* __restrict__ emb,
                         float* __restrict__ x) {
    int i = blockIdx.x * blockDim.x + threadIdx.x;
    if (i < NN) g_cnt[i] = 0;
    if (i < DD) g_gsum[i] = 0.f;
    if (i >= NN * 32) return;
    int n = i >> 5, l = i & 31;
    ((float4*)x)[n * 32 + l] = ((const float4*)emb)[(long long)ids[n] * 32 + l];
}

// ---------------- CSR build (dst-sorted) ----------------
__global__ void k_count(const int* __restrict__ dst) {
    int e = blockIdx.x * blockDim.x + threadIdx.x;
    if (e < NE) atomicAdd(&g_cnt[dst[e]], 1);
}

__global__ void k_scan1() {
    __shared__ int sh[SCAN_B];
    int i = blockIdx.x * SCAN_B + threadIdx.x;
    int v = (i < NN) ? g_cnt[i] : 0;
    sh[threadIdx.x] = v;
    __syncthreads();
    for (int off = 1; off < SCAN_B; off <<= 1) {
        int t = (threadIdx.x >= off) ? sh[threadIdx.x - off] : 0;
        __syncthreads();
        sh[threadIdx.x] += t;
        __syncthreads();
    }
    if (i < NN) g_incl[i] = sh[threadIdx.x];
    if (threadIdx.x == SCAN_B - 1) g_part[blockIdx.x] = sh[SCAN_B - 1];
}

// scan2 folded in: each block reduces the raw per-block sums before its own id.
__global__ void k_scan3() {
    __shared__ int spre;
    if (threadIdx.x == 0) spre = 0;
    __syncthreads();
    int pre = 0;
    for (int j = threadIdx.x; j < blockIdx.x; j += 128) pre += g_part[j];
    if (threadIdx.x < 128 && pre) atomicAdd(&spre, pre);
    __syncthreads();
    int base = spre;
    int i = blockIdx.x * SCAN_B + threadIdx.x;
    if (i < NN) {
        int v = g_incl[i] + base;
        g_rowptr[i + 1] = v;
        g_cursor[i + 1] = v;
        if (i == 0) { g_rowptr[0] = 0; g_cursor[0] = 0; }
    }
}

__global__ void k_scatter(const int* __restrict__ src, const int* __restrict__ dst,
                          const int* __restrict__ etype) {
    int e = blockIdx.x * blockDim.x + threadIdx.x;
    if (e < NE) {
        int p = atomicAdd(&g_cursor[dst[e]], 1);
        g_edge2[p] = make_int2(src[e], etype[e]);
    }
}

// ---------------- once: W -> pre-swizzled fp16 images ----------------
__global__ void k_wconv(const float* __restrict__ Wq, const float* __restrict__ Wk,
                        const float* __restrict__ Wv, const float* __restrict__ Ws) {
    int img = blockIdx.x;  // 0..11
    int l = img >> 2, m = img & 3;
    const float* W =
        ((m == 0) ? Wq : (m == 1) ? Wk : (m == 2) ? Wv : Ws) + (long long)l * DD * DD;
    unsigned char* hi = g_WimgH + img * 32768;
    for (int i = threadIdx.x; i < DD * DD; i += blockDim.x) {
        int k = i >> 7, n = i & 127;  // B(k,n) = W[k][n]
        float w = W[k * DD + n];
        int o = swz(k, n >> 3) + (n & 7) * 2;
        *(__half*)(hi + o) = __float2half(w);
    }
}

// ---------------- all layers: relation projection tables (3 x 1000 x 128) ----------
__global__ void k_erel3(const float* __restrict__ rel, const float* __restrict__ We,
                        const float* __restrict__ be) {
    __shared__ float sr[DD];
    int l = blockIdx.x / NREL, r = blockIdx.x % NREL, j = threadIdx.x;
    const float* W = We + (long long)l * DD * DD;
    sr[j] = rel[r * DD + j];
    __syncthreads();
    float acc = be[l * DD + j];
#pragma unroll 8
    for (int i = 0; i < DD; i++) acc = fmaf(sr[i], W[i * DD + j], acc);
    g_Erelh[(l * NREL + r) * DD + j] = __float2half(acc);
}

// ---------------- mma.sync fused Q/K/V/Skip GEMM (fp16 x fp16, fp32 accum) ------
// R12 configuration: CTA = 128x128, single B buffer, copy overlapped with epilogue.
#define SM_BIAS 0
#define SM_A 2048
#define SM_B (SM_A + 32768)
#define SM_TOT (SM_B + 32768)

__device__ __forceinline__ void copyB_async(uint32_t sbdst, int img, int t) {
    const unsigned char* sh = g_WimgH + img * 32768;
#pragma unroll
    for (int i = 0; i < 8; i++) {
        int o = (t + i * 256) * 16;
        cpa16(sbdst + o, sh + o);
    }
}

__global__ void __launch_bounds__(256, 2)
k_qkvs_mma(const float* __restrict__ x, const float* __restrict__ bq,
           const float* __restrict__ bk, const float* __restrict__ bv,
           const float* __restrict__ bs, int layer) {
    extern __shared__ unsigned char smem[];
    uint32_t sb = smem_u32(smem);
    int t = threadIdx.x, w = t >> 5, lane = t & 31;
    int wr = w & 3, wc = w >> 2;  // 4 row-groups x 2 col-groups
    int rowBase = blockIdx.x * 128;

    copyB_async(sb + SM_B, layer * 4 + 0, t);
    cpa_commit();

    if (t < 128) {
        float* bsm = (float*)(smem + SM_BIAS);
        bsm[t] = bq[t];
        bsm[128 + t] = bk[t];
        bsm[256 + t] = bv[t];
        bsm[384 + t] = bs[t];
    }

    // A tile: fp32 x -> fp16, swizzled smem
#pragma unroll
    for (int it = 0; it < 16; it++) {
        int f4 = t + it * 256;
        int r = f4 >> 5, c4 = (f4 & 31) << 2;
        float4 v = make_float4(0.f, 0.f, 0.f, 0.f);
        if (rowBase + r < NN) v = *(const float4*)&x[(long long)(rowBase + r) * 128 + c4];
        uint2 hp;
        __half2 h01 = __floats2half2_rn(v.x, v.y);
        __half2 h23 = __floats2half2_rn(v.z, v.w);
        hp.x = *(uint32_t*)&h01;
        hp.y = *(uint32_t*)&h23;
        int o = swz(r, c4 >> 3) + (c4 & 7) * 2;
        *(uint2*)(smem + SM_A + o) = hp;
    }

    for (int mi = 0; mi < 4; mi++) {
        cpa_wait<0>();
        __syncthreads();  // B(mi) visible to all warps

        float acc[2][8][4];
#pragma unroll
        for (int a = 0; a < 2; a++)
#pragma unroll
            for (int i = 0; i < 8; i++)
#pragma unroll
                for (int j = 0; j < 4; j++) acc[a][i][j] = 0.f;

        int arow0 = wr * 32 + (lane & 15);
        int bmat = lane >> 3;
        int brow_in = ((bmat & 1) << 3) + (lane & 7);
        int bghalf = bmat >> 1;

#pragma unroll
        for (int ks = 0; ks < 8; ks++) {
            uint32_t ah[2][4];
            int ag = ks * 2 + (lane >> 4);
#pragma unroll
            for (int mt = 0; mt < 2; mt++) {
                uint32_t aaddr = sb + SM_A + swz(arow0 + mt * 16, ag);
                ldm_x4(ah[mt][0], ah[mt][1], ah[mt][2], ah[mt][3], aaddr);
            }
            int brow = ks * 16 + brow_in;
            uint32_t bh[4][4];
#pragma unroll
            for (int np = 0; np < 4; np++) {
                uint32_t baddr = sb + SM_B + swz(brow, wc * 8 + np * 2 + bghalf);
                ldm_x4t(bh[np][0], bh[np][1], bh[np][2], bh[np][3], baddr);
            }
#pragma unroll
            for (int np = 0; np < 4; np++)
#pragma unroll
                for (int mt = 0; mt < 2; mt++) {
                    mma_f16(acc[mt][np * 2], ah[mt], bh[np][0], bh[np][1]);
                    mma_f16(acc[mt][np * 2 + 1], ah[mt], bh[np][2], bh[np][3]);
                }
        }

        __syncthreads();
        if (mi < 3) {
            copyB_async(sb + SM_B, layer * 4 + mi + 1, t);
            cpa_commit();
        }

        // epilogue; K/V interleave into g_KV (K at +0, V at +128; row stride 256)
        float* outp;
        int rstride;
        if (mi == 0) { outp = g_Q; rstride = 128; }
        else if (mi == 1) { outp = g_KV; rstride = 256; }
        else if (mi == 2) { outp = g_KV + 128; rstride = 256; }
        else { outp = g_S; rstride = 128; }
        const float* bsm = (const float*)(smem + SM_BIAS) + mi * 128;
        int cb = wc * 64 + (lane & 3) * 2;
#pragma unroll
        for (int mt = 0; mt < 2; mt++) {
            int r0 = rowBase + wr * 32 + mt * 16 + (lane >> 2);
#pragma unroll
            for (int nt = 0; nt < 8; nt++) {
                int col = cb + nt * 8;
                float2 b2 = make_float2(bsm[col], bsm[col + 1]);
                if (r0 < NN) {
                    float2 o0 = make_float2(acc[mt][nt][0] + b2.x, acc[mt][nt][1] + b2.y);
                    *(float2*)&outp[(long long)r0 * rstride + col] = o0;
                }
                if (r0 + 8 < NN) {
                    float2 o1 = make_float2(acc[mt][nt][2] + b2.x, acc[mt][nt][3] + b2.y);
                    *(float2*)&outp[(long long)(r0 + 8) * rstride + col] = o1;
                }
            }
        }
    }
}

// ---------------- fused attention / softmax / aggregate / LN / residual ----------------
// NN = 100000 = 12500 blocks * 8 warps exactly. 4-edge unrolled online softmax (R9 form).
__global__ void k_attn(float* __restrict__ x, const float* __restrict__ lng,
                       const float* __restrict__ lnb, int ebase, int last) {
    __shared__ float sums[DD];
    int n = blockIdx.x * (blockDim.x >> 5) + (threadIdx.x >> 5);
    int lane = threadIdx.x & 31;

    const float4* Q4 = (const float4*)g_Q;
    const float4* KV4 = (const float4*)g_KV;

    float4 q = Q4[n * 32 + lane];
    int beg = g_rowptr[n], end = g_rowptr[n + 1];

    float m = -3.4e38f, dsum = 0.f;
    float4 acc = make_float4(0.f, 0.f, 0.f, 0.f);

    int idx = beg;
#define EDGE_LOAD(i, e)                                                    \
    float4 kv##i = KV4[(e).x * 64 + lane];                                 \
    float4 vv##i = KV4[(e).x * 64 + 32 + lane];                            \
    uint2 er##i = *(const uint2*)&g_Erelh[ebase + (e).y * 128 + lane * 4]; \
    float4 ev##i = h4_to_f4(er##i);
#define EDGE_DOT(i)                                                      \
    float p##i = q.x * (kv##i.x + ev##i.x) + q.y * (kv##i.y + ev##i.y) + \
                 q.z * (kv##i.z + ev##i.z) + q.w * (kv##i.w + ev##i.w);  \
    p##i += __shfl_xor_sync(0xffffffffu, p##i, 1);                       \
    p##i += __shfl_xor_sync(0xffffffffu, p##i, 2);                       \
    float a##i = p##i * 0.25f;
#define EDGE_ACC(i)                      \
    acc.x += w##i * (vv##i.x + ev##i.x); \
    acc.y += w##i * (vv##i.y + ev##i.y); \
    acc.z += w##i * (vv##i.z + ev##i.z); \
    acc.w += w##i * (vv##i.w + ev##i.w);

    for (; idx + 3 < end; idx += 4) {
        int2 e0 = g_edge2[idx];
        int2 e1 = g_edge2[idx + 1];
        int2 e2 = g_edge2[idx + 2];
        int2 e3 = g_edge2[idx + 3];
        EDGE_LOAD(0, e0) EDGE_LOAD(1, e1) EDGE_LOAD(2, e2) EDGE_LOAD(3, e3)
        EDGE_DOT(0) EDGE_DOT(1) EDGE_DOT(2) EDGE_DOT(3)
        float mn = fmaxf(fmaxf(m, fmaxf(a0, a1)), fmaxf(a2, a3));
        float sc = __expf(m - mn);
        float w0 = __expf(a0 - mn), w1 = __expf(a1 - mn);
        float w2 = __expf(a2 - mn), w3 = __expf(a3 - mn);
        dsum = dsum * sc + w0 + w1 + w2 + w3;
        acc.x *= sc; acc.y *= sc; acc.z *= sc; acc.w *= sc;
        EDGE_ACC(0) EDGE_ACC(1) EDGE_ACC(2) EDGE_ACC(3)
        m = mn;
    }
    for (; idx < end; idx++) {
        int2 e0 = g_edge2[idx];
        EDGE_LOAD(0, e0)
        EDGE_DOT(0)
        float mn = fmaxf(m, a0);
        float sc = __expf(m - mn);
        float w0 = __expf(a0 - mn);
        dsum = dsum * sc + w0;
        acc.x *= sc; acc.y *= sc; acc.z *= sc; acc.w *= sc;
        EDGE_ACC(0)
        m = mn;
    }

    float inv = (dsum > 0.f) ? (1.f / dsum) : 0.f;
    float4 sk = ((const float4*)g_S)[n * 32 + lane];
    float4 o = make_float4(acc.x * inv + sk.x, acc.y * inv + sk.y, acc.z * inv + sk.z,
                           acc.w * inv + sk.w);

    float sum = o.x + o.y + o.z + o.w;
#pragma unroll
    for (int off = 16; off; off >>= 1) sum += __shfl_xor_sync(0xffffffffu, sum, off);
    float mean = sum * (1.f / 128.f);
    float4 c = make_float4(o.x - mean, o.y - mean, o.z - mean, o.w - mean);
    float ss = c.x * c.x + c.y * c.y + c.z * c.z + c.w * c.w;
#pragma unroll
    for (int off = 16; off; off >>= 1) ss += __shfl_xor_sync(0xffffffffu, ss, off);
    float var = ss * (1.f / 128.f);
    float rstd = rsqrtf(var + 1e-5f);

    float4 g = ((const float4*)lng)[lane];
    float4 b = ((const float4*)lnb)[lane];
    float4 y;
    y.x = fmaxf(c.x * rstd * g.x + b.x, 0.f);
    y.y = fmaxf(c.y * rstd * g.y + b.y, 0.f);
    y.z = fmaxf(c.z * rstd * g.z + b.z, 0.f);
    y.w = fmaxf(c.w * rstd * g.w + b.w, 0.f);

    float4 xo = ((float4*)x)[n * 32 + lane];
    xo.x += y.x;
    xo.y += y.y;
    xo.z += y.z;
    xo.w += y.w;
    ((float4*)x)[n * 32 + lane] = xo;

    if (last) {
        if (threadIdx.x < DD) sums[threadIdx.x] = 0.f;
        __syncthreads();
        atomicAdd(&sums[lane * 4 + 0], xo.x);
        atomicAdd(&sums[lane * 4 + 1], xo.y);
        atomicAdd(&sums[lane * 4 + 2], xo.z);
        atomicAdd(&sums[lane * 4 + 3], xo.w);
        __syncthreads();
        if (threadIdx.x < DD) atomicAdd(&g_gsum[threadIdx.x], sums[threadIdx.x]);
    }
}

__global__ void k_final(float* __restrict__ gout) {
    int c = threadIdx.x;
    if (c < DD) gout[c] = g_gsum[c] * (1.f / (float)NN);
}

// ---------------- launch ----------------
extern "C" void kernel_launch(void* const* d_in, const int* in_sizes, int n_in,
                              void* d_out, int out_size) {
    const int* node_ids = (const int*)d_in[0];
    const int* edge_index = (const int*)d_in[1];
    const int* edge_type = (const int*)d_in[2];
    const float* ent_emb = (const float*)d_in[3];
    const float* rel_emb = (const float*)d_in[4];
    const float* Wq = (const float*)d_in[5];
    const float* bq = (const float*)d_in[6];
    const float* Wk = (const float*)d_in[7];
    const float* bk = (const float*)d_in[8];
    const float* Wv = (const float*)d_in[9];
    const float* bv = (const float*)d_in[10];
    const float* We = (const float*)d_in[11];
    const float* be = (const float*)d_in[12];
    const float* Ws = (const float*)d_in[13];
    const float* bs = (const float*)d_in[14];
    const float* lng = (const float*)d_in[15];
    const float* lnb = (const float*)d_in[16];

    float* x = (float*)d_out;
    float* gout = (float*)d_out + (out_size - DD);

    const int* src = edge_index;
    const int* dst = edge_index + NE;

    cudaFuncSetAttribute(k_qkvs_mma, cudaFuncAttributeMaxDynamicSharedMemorySize, SM_TOT);

    // launches 1-4: keep layer-0 GEMM in the ncu capture slot (4th launch)
    k_gather<<<(NN * 32 + 255) / 256, 256>>>(node_ids, ent_emb, x);
    k_wconv<<<12, 256>>>(Wq, Wk, Wv, Ws);
    k_erel3<<<NLAYER * NREL, DD>>>(rel_emb, We, be);
    k_qkvs_mma<<<(NN + 127) / 128, 256, SM_TOT>>>(x, bq, bk, bv, bs, 0);

    // CSR build (needed before first k_attn)
    k_count<<<(NE + 255) / 256, 256>>>(dst);
    k_scan1<<<SCAN_NB, SCAN_B>>>();
    k_scan3<<<SCAN_NB, SCAN_B>>>();
    k_scatter<<<(NE + 255) / 256, 256>>>(src, dst, edge_type);

    k_attn<<<NN / 8, 256>>>(x, lng, lnb, 0, 0);

    for (int l = 1; l < NLAYER; l++) {
        int bo = l * DD;
        k_qkvs_mma<<<(NN + 127) / 128, 256, SM_TOT>>>(x, bq + bo, bk + bo, bv + bo, bs + bo, l);
        k_attn<<<NN / 8, 256>>>(x, lng + bo, lnb + bo, l * NREL * DD, l == NLAYER - 1);
    }

    k_final<<<1, DD>>>(gout);
}